// round 3
// baseline (speedup 1.0000x reference)
#include <cuda_runtime.h>
#include <math_constants.h>

// B=8, U=V=13 (UV=169), H=128, W=160 (HW=20480), TRUNC=4, disp -6..6
#define UV 169
#define VD 13
#define HW 20480
#define PIX 32                  // pixels per CTA
#define NT 128                  // 4 threads cooperate per pixel
#define RSTRIDE 21              // padded row: v-slot for v in [-4,16]
#define NROWS 14                // u rows 0..12 + all-pad row 13
#define SLAB (NROWS * RSTRIDE)  // 294 floats per pixel
#define SMEM_FLOATS (PIX * SLAB)   // 9408 floats = 37632 B (< 48KB static)
#define NEGBIG (-1e30f)

__global__ __launch_bounds__(NT, 6)
void flow_regression_kernel(const float* __restrict__ x, float* __restrict__ out) {
    __shared__ float s[SMEM_FLOATS];   // s[pix][14][21]

    const int tid   = threadIdx.x;
    const int blk   = blockIdx.x;            // 0 .. 8*640-1
    const int b     = blk / (HW / PIX);
    const int chunk = blk % (HW / PIX);

    const float* xb = x + b * (UV * HW) + chunk * PIX;

    // ---- Phase 0: fill entire slab with -1e30 (pads -> exp()==0) ----
    {
        const float4 nb = make_float4(NEGBIG, NEGBIG, NEGBIG, NEGBIG);
        #pragma unroll 4
        for (int i = tid; i < SMEM_FLOATS / 4; i += NT)
            ((float4*)s)[i] = nb;
    }
    __syncthreads();

    // ---- Phase 1: load 169 planes x 32 floats, transposed into padded slabs ----
    // thread -> o = float4 slot within 32-pixel chunk (8), vl = v plane lane (16, 13 active)
    {
        const int o  = tid & 7;
        const int vl = tid >> 3;
        if (vl < VD) {
            const float* g = xb + vl * HW + o * 4;
            float* d = s + (o * 4) * SLAB + vl + 4;   // row u=0, pixel o*4
            #pragma unroll
            for (int u = 0; u < VD; u++) {
                float4 v = *(const float4*)g;
                d[0 * SLAB] = v.x;
                d[1 * SLAB] = v.y;
                d[2 * SLAB] = v.z;
                d[3 * SLAB] = v.w;
                g += VD * HW;       // next u plane
                d += RSTRIDE;       // next slab row
            }
        }
    }
    __syncthreads();

    const int sub = tid & 3;        // quarter of per-pixel work
    const int p   = tid >> 2;       // pixel 0..31
    const float* sp = s + p * SLAB;

    // ---- Pass A: argmax over 169 (ascending uv order per lane; ties -> lowest uv) ----
    float m  = -CUDART_INF_F;
    int   am = 0;
    {
        const float* r = sp + 4 + sub;   // v slot for dv=sub
        #pragma unroll
        for (int u = 0; u < VD; u++) {
            #pragma unroll
            for (int j = 0; j < 3; j++) {           // v = sub, sub+4, sub+8 (<=11)
                float v = r[j * 4];
                int idx = u * VD + sub + j * 4;
                if (v > m) { m = v; am = idx; }
            }
            if (sub == 0) {                          // v = 12 handled by sub 0
                float v = r[12];
                int idx = u * VD + 12;
                if (v > m) { m = v; am = idx; }
            }
            r += RSTRIDE;
        }
    }
    // combine across the 4 lanes of this pixel (first-occurrence tie-break)
    #pragma unroll
    for (int off = 1; off <= 2; off <<= 1) {
        float mo = __shfl_xor_sync(0xffffffffu, m,  off);
        int   ao = __shfl_xor_sync(0xffffffffu, am, off);
        if (mo > m || (mo == m && ao < am)) { m = mo; am = ao; }
    }
    const int ui = am / VD;
    const int vi = am - ui * VD;

    // ---- Pass B: 9x9 window softmax, no bounds checks (pads are -1e30 -> e=0) ----
    // element (du,dv): slab offset = row*21 + vi + dv, dv = sub + 4*j
    float Z = 0.0f, sU = 0.0f, sV = 0.0f;
    {
        const float* bp = sp + vi + sub;
        const float wu0 = (float)(ui - 10);          // u-6 = ui + du - 10
        const float wv0 = (float)(vi + sub - 10);    // v-6 = vi + dv - 10
        #pragma unroll
        for (int du = 0; du < 9; du++) {
            int u = ui + du - 4;
            int row = ((unsigned)u <= 12u) ? u : 13; // out-of-range -> pad row
            const float* r = bp + row * RSTRIDE;
            float wu = wu0 + (float)du;
            #pragma unroll
            for (int j = 0; j < 2; j++) {            // dv = sub, sub+4 (always <= 8)
                float e = __expf(r[j * 4] - m);
                Z  += e;
                sU += e * wu;
                sV += e * (wv0 + (float)(j * 4));
            }
            if (sub == 0) {                          // dv = 8 handled by sub 0
                float e = __expf(r[8] - m);
                Z  += e;
                sU += e * wu;
                sV += e * (wv0 + 8.0f);
            }
        }
    }
    #pragma unroll
    for (int off = 1; off <= 2; off <<= 1) {
        Z  += __shfl_xor_sync(0xffffffffu, Z,  off);
        sU += __shfl_xor_sync(0xffffffffu, sU, off);
        sV += __shfl_xor_sync(0xffffffffu, sV, off);
    }

    if (sub == 0) {
        const float inv = __frcp_rn(Z);
        const int pix = chunk * PIX + p;
        out[(b * 2 + 0) * HW + pix] = sU * inv;
        out[(b * 2 + 1) * HW + pix] = sV * inv;
    }
}

extern "C" void kernel_launch(void* const* d_in, const int* in_sizes, int n_in,
                              void* d_out, int out_size) {
    (void)in_sizes; (void)n_in; (void)out_size;
    const float* x = (const float*)d_in[0];
    float* out = (float*)d_out;

    const int nblocks = 8 * (HW / PIX);   // 5120
    flow_regression_kernel<<<nblocks, NT>>>(x, out);
}